// round 1
// baseline (speedup 1.0000x reference)
#include <cuda_runtime.h>
#include <cuda_bf16.h>
#include <cstdint>

#define W 256
#define BH 32
#define NIMG 128
#define NBANDS 8
#define NBLOCKS (NIMG * NBANDS)   // 1024
#define TOTAL_ELEMS 8388608.0     // 128*256*256

__device__ float g_partials[NBLOCKS];

// Gaussian taps: computed in double exactly as numpy (exp in f64, normalize in f64, cast f32)
constexpr double E2d  = 0.1353352832366127;   // exp(-2)
constexpr double E05d = 0.6065306597126334;   // exp(-0.5)
constexpr double GSUM = 1.0 + 2.0 * (E2d + E05d);
constexpr float  G0 = (float)(E2d / GSUM);
constexpr float  G1 = (float)(E05d / GSUM);
constexpr float  G2 = (float)(1.0 / GSUM);

// Orientation bin boundaries: k = 4 + round(atan2(gy,gx) * 4/3.14159), idx = k & 7.
// Boundaries b_m = (m+0.5)*3.14159/4 are slightly skewed vs pi/8 multiples, and the
// skew differs per quadrant (pi - b is not another boundary). Quadrant-exact tangents:
#define TLO_POS 0.414213174f   // tan(0.5*3.14159/4)
#define THI_POS 2.414206767f   // tan(1.5*3.14159/4)
#define TLO_NEG 0.414216283f   // tan(pi - 3.5*3.14159/4)
#define THI_NEG 2.414224887f   // tan(pi - 2.5*3.14159/4)

__device__ __forceinline__ int dir_idx(float gx, float gy) {
    float ax = fabsf(gx), ay = fabsf(gy);
    bool xn = gx < 0.0f;
    float tlo = xn ? TLO_NEG : TLO_POS;
    float thi = xn ? THI_NEG : THI_POS;
    int s = (ay >= ax * tlo) ? ((ay > ax * thi) ? 2 : 1) : 0;
    int kp = xn ? (4 - s) : s;
    int k = (gy < 0.0f) ? (4 - kp) : (4 + kp);
    return k & 7;
}

__device__ __forceinline__ int mod3(int r) { return (r + 300) % 3; }

// NMS neighbor offset tables packed in nibbles: (dr+1), (dc+1) per idx
#define DRP 0x00012221u
#define DCP 0x21000122u

__global__ __launch_bounds__(256) void canny_band(const float* __restrict__ in0,
                                                  const float* __restrict__ in1) {
    const int t    = threadIdx.x;          // column 0..255
    const int blk  = blockIdx.x;
    const int n    = blk >> 3;             // image
    const int band = blk & 7;
    const int r0   = band * BH;
    const float* base0 = in0 + n * (W * W);
    const float* base1 = in1 + n * (W * W);

    __shared__ float sh_prep[2][W + 4];      // halo 2 each side
    __shared__ float sh_bl[2][3][W + 2];     // blurred ring, halo 1
    __shared__ float sh_mag[2][3][W + 2];    // magnitude ring, halo 1
    __shared__ float red[256];

    // zero guard cells once
    if (t < 2) {
        #pragma unroll
        for (int im = 0; im < 2; im++) {
            sh_prep[im][t] = 0.0f;
            sh_prep[im][W + 2 + t] = 0.0f;
            #pragma unroll
            for (int rr = 0; rr < 3; rr++) {
                sh_bl[im][rr][t * (W + 1)] = 0.0f;   // t=0 -> [0], t=1 -> [257]
                sh_mag[im][rr][t * (W + 1)] = 0.0f;
            }
        }
    }

    float hb0[5] = {0, 0, 0, 0, 0};
    float hb1[5] = {0, 0, 0, 0, 0};
    float cmag0 = 0.0f, cmag1 = 0.0f;   // delayed center mag (row er)
    int   cidx0 = 0,    cidx1 = 0;      // delayed center orientation idx
    float acc = 0.0f;

    __syncthreads();

    for (int ir = r0 - 4; ir < r0 + BH + 4; ++ir) {
        // ---- Stage A: load + prep row ir ----
        float p0 = 0.0f, p1 = 0.0f;
        if ((unsigned)ir < (unsigned)W) {
            p0 = (base0[ir * W + t] + 1.0f) * 0.5f;
            p1 = (base1[ir * W + t] + 1.0f) * 0.5f;
        }
        sh_prep[0][t + 2] = p0;
        sh_prep[1][t + 2] = p1;
        __syncthreads();

        // ---- Stage B: horizontal blur -> reg ring; vertical blur -> shared ring ----
        float h0 = G0 * (sh_prep[0][t] + sh_prep[0][t + 4])
                 + G1 * (sh_prep[0][t + 1] + sh_prep[0][t + 3])
                 + G2 * sh_prep[0][t + 2];
        float h1 = G0 * (sh_prep[1][t] + sh_prep[1][t + 4])
                 + G1 * (sh_prep[1][t + 1] + sh_prep[1][t + 3])
                 + G2 * sh_prep[1][t + 2];
        hb0[0] = hb0[1]; hb0[1] = hb0[2]; hb0[2] = hb0[3]; hb0[3] = hb0[4]; hb0[4] = h0;
        hb1[0] = hb1[1]; hb1[1] = hb1[2]; hb1[2] = hb1[3]; hb1[3] = hb1[4]; hb1[4] = h1;

        const int br = ir - 2;
        if (br >= r0 - 2) {
            float v0 = 0.0f, v1 = 0.0f;
            if ((unsigned)br < (unsigned)W) {
                v0 = G0 * (hb0[0] + hb0[4]) + G1 * (hb0[1] + hb0[3]) + G2 * hb0[2];
                v1 = G0 * (hb1[0] + hb1[4]) + G1 * (hb1[1] + hb1[3]) + G2 * hb1[2];
            }
            const int s = mod3(br);
            sh_bl[0][s][t + 1] = v0;
            sh_bl[1][s][t + 1] = v1;
        }
        __syncthreads();

        // ---- Stage C: Sobel + magnitude + orientation for row mr ----
        const int mr = ir - 3;
        float nm0 = 0.0f, nm1 = 0.0f;
        int   ni0 = 0,    ni1 = 0;
        if (mr >= r0 - 1) {
            if ((unsigned)mr < (unsigned)W) {
                const int su = mod3(mr - 1), sc = mod3(mr), sd = mod3(mr + 1);
                #pragma unroll
                for (int im = 0; im < 2; im++) {
                    float a  = sh_bl[im][su][t];
                    float b  = sh_bl[im][su][t + 1];
                    float c  = sh_bl[im][su][t + 2];
                    float d  = sh_bl[im][sc][t];
                    float f  = sh_bl[im][sc][t + 2];
                    float g  = sh_bl[im][sd][t];
                    float h  = sh_bl[im][sd][t + 1];
                    float i2 = sh_bl[im][sd][t + 2];
                    float gx = (a - c) + 2.0f * (d - f) + (g - i2);
                    float gy = (a - g) + 2.0f * (b - h) + (c - i2);
                    float m  = sqrtf(gx * gx + gy * gy);
                    int   id = dir_idx(gx, gy);
                    if (im == 0) { nm0 = m; ni0 = id; } else { nm1 = m; ni1 = id; }
                }
            }
            const int s = mod3(mr);
            sh_mag[0][s][t + 1] = nm0;
            sh_mag[1][s][t + 1] = nm1;
        }
        __syncthreads();

        // ---- Stage D: NMS + threshold + |diff| for row er ----
        const int er = ir - 4;
        if (er >= r0) {
            float e0, e1;
            {
                int idx = cidx0;
                int dr = (int)((DRP >> (idx * 4)) & 3u) - 1;
                int dc = (int)((DCP >> (idx * 4)) & 3u) - 1;
                float np = sh_mag[0][mod3(er + dr)][t + 1 + dc];
                float nn = sh_mag[0][mod3(er - dr)][t + 1 - dc];
                float m = cmag0;
                bool ismax = fminf(m - np, m - nn) > 0.0f;
                e0 = (ismax && m >= 2.0f) ? m : 0.0f;
            }
            {
                int idx = cidx1;
                int dr = (int)((DRP >> (idx * 4)) & 3u) - 1;
                int dc = (int)((DCP >> (idx * 4)) & 3u) - 1;
                float np = sh_mag[1][mod3(er + dr)][t + 1 + dc];
                float nn = sh_mag[1][mod3(er - dr)][t + 1 - dc];
                float m = cmag1;
                bool ismax = fminf(m - np, m - nn) > 0.0f;
                e1 = (ismax && m >= 2.0f) ? m : 0.0f;
            }
            acc += fabsf(e0 - e1);
        }
        // advance delay registers (row mr computed this iter is row er of next iter)
        cmag0 = nm0; cidx0 = ni0;
        cmag1 = nm1; cidx1 = ni1;
    }

    // deterministic block reduction
    red[t] = acc;
    __syncthreads();
    #pragma unroll
    for (int off = 128; off > 0; off >>= 1) {
        if (t < off) red[t] += red[t + off];
        __syncthreads();
    }
    if (t == 0) g_partials[blk] = red[0];
}

__global__ __launch_bounds__(256) void final_reduce(float* __restrict__ out) {
    const int t = threadIdx.x;
    double s = 0.0;
    for (int i = t; i < NBLOCKS; i += 256) s += (double)g_partials[i];
    __shared__ double sd[256];
    sd[t] = s;
    __syncthreads();
    #pragma unroll
    for (int off = 128; off > 0; off >>= 1) {
        if (t < off) sd[t] += sd[t + off];
        __syncthreads();
    }
    if (t == 0) out[0] = (float)(sd[0] / TOTAL_ELEMS);
}

extern "C" void kernel_launch(void* const* d_in, const int* in_sizes, int n_in,
                              void* d_out, int out_size) {
    const float* gt = (const float*)d_in[0];   // data_input
    const float* pr = (const float*)d_in[1];   // model_output
    canny_band<<<NBLOCKS, 256>>>(gt, pr);
    final_reduce<<<1, 256>>>((float*)d_out);
}

// round 2
// speedup vs baseline: 1.2592x; 1.2592x over previous
#include <cuda_runtime.h>
#include <cuda_bf16.h>
#include <cstdint>

#define W 256
#define BH 32
#define NBLOCKS 1024          // 128 images * 8 bands

__device__ float g_partials[NBLOCKS];
__device__ unsigned int g_ticket;   // zero-init; atomicInc wraps to 0 after NBLOCKS -> replay-safe

// Gaussian taps, computed as numpy does (f64 exp, f64 normalize, cast f32)
constexpr double E2d  = 0.1353352832366127;   // exp(-2)
constexpr double E05d = 0.6065306597126334;   // exp(-0.5)
constexpr double GSUM = 1.0 + 2.0 * (E2d + E05d);
constexpr float  G0 = (float)(E2d / GSUM);
constexpr float  G1 = (float)(E05d / GSUM);
constexpr float  G2 = (float)(1.0 / GSUM);

// Quadrant-exact tangent thresholds for k = 4 + round(atan2(gy,gx)*4/3.14159)
#define TLO_POS 0.414213174f
#define THI_POS 2.414206767f
#define TLO_NEG 0.414216283f
#define THI_NEG 2.414224887f

__device__ __forceinline__ int dir_idx(float gx, float gy) {
    float ax = fabsf(gx), ay = fabsf(gy);
    bool xn = gx < 0.0f;
    float tlo = xn ? TLO_NEG : TLO_POS;
    float thi = xn ? THI_NEG : THI_POS;
    int s = (ay >= ax * tlo) ? ((ay > ax * thi) ? 2 : 1) : 0;
    int kp = xn ? (4 - s) : s;
    int k = (gy < 0.0f) ? (4 - kp) : (4 + kp);
    return k & 7;
}

// NMS neighbor offsets packed in nibbles: (dr+1),(dc+1) per idx
#define DRP 0x00012221u
#define DCP 0x21000122u

__global__ __launch_bounds__(256) void canny_fused(const float* __restrict__ in0,
                                                   const float* __restrict__ in1,
                                                   float* __restrict__ out) {
    const int t   = threadIdx.x;            // column
    const int blk = blockIdx.x;
    const int n   = blk >> 3;               // image
    const int r0  = (blk & 7) * BH;         // band start row
    const float* b0 = in0 + n * (W * W);
    const float* b1 = in1 + n * (W * W);

    __shared__ float2 sh_prep[2][W + 4];    // double-buffered, halo 2/side
    __shared__ float2 sh_bl[2][W + 2];      // blurred ring (depth 2), halo 1/side
    __shared__ float2 sh_mag[4][W + 2];     // magnitude ring (depth 4), halo 1/side
    __shared__ float  red[256];
    __shared__ double sdd[256];
    __shared__ unsigned s_last;

    // zero ALL stencil shared memory once (makes early-pipeline reads well-defined)
    {
        float2 z = make_float2(0.f, 0.f);
        for (int i = t; i < 2 * (W + 4); i += 256) ((float2*)sh_prep)[i] = z;
        for (int i = t; i < 2 * (W + 2); i += 256) ((float2*)sh_bl)[i]   = z;
        for (int i = t; i < 4 * (W + 2); i += 256) ((float2*)sh_mag)[i]  = z;
    }

    // register rings (x = image0, y = image1)
    float2 hb0, hb1, hb2, hb3, hb4;               // hblur rows ir-5..ir-1
    hb0 = hb1 = hb2 = hb3 = hb4 = make_float2(0.f, 0.f);
    float2 A0, A1, A2, B0, B1, B2;                // Sobel row aggregates, rows ab-2..ab
    A0 = A1 = A2 = B0 = B1 = B2 = make_float2(0.f, 0.f);
    float2 d1m = make_float2(0.f, 0.f), d2m = make_float2(0.f, 0.f);  // mag delay (1,2 iters)
    int d1i0 = 0, d1i1 = 0, d2i0 = 0, d2i1 = 0;   // idx delay
    float acc = 0.f;

    __syncthreads();

    // Pipeline at iteration ir (one barrier per iteration):
    //   load row ir -> sh_prep[ir&1]
    //   hblur row ir-1 (reads sh_prep[(ir-1)&1], written last iter)
    //   vblur row ir-3 (register ring) -> sh_bl[(ir-3)&1]
    //   A/B row  ir-4 (reads sh_bl[(ir-4)&1], written last iter) -> register rings
    //   sobel+mag row ir-5 (registers only) -> sh_mag[(ir-5)&3]
    //   NMS row ir-7 (reads sh_mag rows ir-8..ir-6, all written in prior iters)
    #pragma unroll 2
    for (int ir = r0 - 4; ir <= r0 + BH + 6; ++ir) {
        // global load (no shared access, safe before the barrier)
        float2 p = make_float2(0.f, 0.f);
        if ((unsigned)ir < (unsigned)W) {
            p.x = (b0[ir * W + t] + 1.0f) * 0.5f;
            p.y = (b1[ir * W + t] + 1.0f) * 0.5f;
        }

        __syncthreads();   // the single barrier: separates prior-iter reads from this-iter writes

        sh_prep[ir & 1][t + 2] = p;

        // ---- hblur row ir-1 ----
        {
            const float2* pr = sh_prep[(ir - 1) & 1];
            float2 a0 = pr[t], a1 = pr[t + 1], a2 = pr[t + 2], a3 = pr[t + 3], a4 = pr[t + 4];
            float2 h;
            h.x = G0 * (a0.x + a4.x) + G1 * (a1.x + a3.x) + G2 * a2.x;
            h.y = G0 * (a0.y + a4.y) + G1 * (a1.y + a3.y) + G2 * a2.y;
            hb0 = hb1; hb1 = hb2; hb2 = hb3; hb3 = hb4; hb4 = h;
        }

        // ---- vblur row br = ir-3 -> sh_bl ----
        {
            const int br = ir - 3;
            float2 v = make_float2(0.f, 0.f);
            if ((unsigned)br < (unsigned)W) {
                v.x = G0 * (hb0.x + hb4.x) + G1 * (hb1.x + hb3.x) + G2 * hb2.x;
                v.y = G0 * (hb0.y + hb4.y) + G1 * (hb1.y + hb3.y) + G2 * hb2.y;
            }
            sh_bl[br & 1][t + 1] = v;
        }

        // ---- A/B aggregates for row ab = ir-4 ----
        {
            const float2* bl = sh_bl[(ir - 4) & 1];
            float2 l = bl[t], c = bl[t + 1], r = bl[t + 2];
            float2 A, Bv;
            A.x  = l.x + 2.0f * c.x + r.x;
            A.y  = l.y + 2.0f * c.y + r.y;
            Bv.x = l.x - r.x;
            Bv.y = l.y - r.y;
            A0 = A1; A1 = A2; A2 = A;
            B0 = B1; B1 = B2; B2 = Bv;
        }

        // ---- Sobel + magnitude + orientation for row mr = ir-5 ----
        float2 nm = make_float2(0.f, 0.f);
        int ni0 = 0, ni1 = 0;
        {
            const int mr = ir - 5;
            if ((unsigned)mr < (unsigned)W) {
                float gx0 = B0.x + 2.0f * B1.x + B2.x;
                float gy0 = A0.x - A2.x;
                nm.x = sqrtf(gx0 * gx0 + gy0 * gy0);
                ni0  = dir_idx(gx0, gy0);
                float gx1 = B0.y + 2.0f * B1.y + B2.y;
                float gy1 = A0.y - A2.y;
                nm.y = sqrtf(gx1 * gx1 + gy1 * gy1);
                ni1  = dir_idx(gx1, gy1);
            }
            sh_mag[mr & 3][t + 1] = nm;
        }

        // ---- NMS + threshold + |diff| for row er = ir-7 ----
        {
            const int er = ir - 7;
            if (er >= r0 && er < r0 + BH) {
                float e0, e1;
                {
                    int idx = d2i0;
                    int dr = (int)((DRP >> (idx * 4)) & 3u) - 1;
                    int dc = (int)((DCP >> (idx * 4)) & 3u) - 1;
                    float np = sh_mag[(er + dr) & 3][t + 1 + dc].x;
                    float nn = sh_mag[(er - dr) & 3][t + 1 - dc].x;
                    float m  = d2m.x;
                    e0 = (fminf(m - np, m - nn) > 0.0f && m >= 2.0f) ? m : 0.0f;
                }
                {
                    int idx = d2i1;
                    int dr = (int)((DRP >> (idx * 4)) & 3u) - 1;
                    int dc = (int)((DCP >> (idx * 4)) & 3u) - 1;
                    float np = sh_mag[(er + dr) & 3][t + 1 + dc].y;
                    float nn = sh_mag[(er - dr) & 3][t + 1 - dc].y;
                    float m  = d2m.y;
                    e1 = (fminf(m - np, m - nn) > 0.0f && m >= 2.0f) ? m : 0.0f;
                }
                acc += fabsf(e0 - e1);
            }
        }

        // advance delay registers
        d2m = d1m; d1m = nm;
        d2i0 = d1i0; d1i0 = ni0;
        d2i1 = d1i1; d1i1 = ni1;
    }

    // deterministic block reduction
    red[t] = acc;
    __syncthreads();
    #pragma unroll
    for (int off = 128; off > 0; off >>= 1) {
        if (t < off) red[t] += red[t + off];
        __syncthreads();
    }

    if (t == 0) {
        g_partials[blk] = red[0];
        __threadfence();
        unsigned old = atomicInc(&g_ticket, NBLOCKS - 1);   // wraps to 0 -> replay-safe
        s_last = (old == NBLOCKS - 1) ? 1u : 0u;
    }
    __syncthreads();

    // last block deterministically reduces all partials (double precision)
    if (s_last) {
        double s = 0.0;
        for (int i = t; i < NBLOCKS; i += 256) s += (double)__ldcg(&g_partials[i]);
        sdd[t] = s;
        __syncthreads();
        #pragma unroll
        for (int off = 128; off > 0; off >>= 1) {
            if (t < off) sdd[t] += sdd[t + off];
            __syncthreads();
        }
        if (t == 0) out[0] = (float)(sdd[0] / 8388608.0);
    }
}

extern "C" void kernel_launch(void* const* d_in, const int* in_sizes, int n_in,
                              void* d_out, int out_size) {
    const float* gt = (const float*)d_in[0];   // data_input
    const float* pr = (const float*)d_in[1];   // model_output
    canny_fused<<<NBLOCKS, 256>>>(gt, pr, (float*)d_out);
}